// round 13
// baseline (speedup 1.0000x reference)
#include <cuda_runtime.h>
#include <cstdint>

#define N_NODES 100000
#define CH      128
#define N_REL   16
#define N_EDGES 200000
#define NW      17                        /* self + 16 relations */
#define TM      64                        /* tile rows */
#define NT      ((N_NODES + TM - 1) / TM) /* 1563 dst tiles */
#define NBK     (NT * N_REL * 4)          /* 100032 buckets (tile,rel,gwarp) */
#define HS      132                       /* hA row stride (floats) */
#define HSZ     (TM * HS)                 /* 8448 floats per hA buffer */
#define SMEM_FLOATS (2 * HSZ)             /* 16896 floats = 67584 B -> 2+ CTA/SM */

// ---------------- device scratch ----------------
__device__ unsigned      g_emeta[N_REL * N_EDGES];   // src | dl<<17 (sorted by bucket)
__device__ float         g_B[NW * CH * CH];          // tf32-rounded weights
__device__ int           g_deg[N_REL * N_NODES];
__device__ float         g_invdeg[N_REL * N_NODES];
__device__ int           g_bcnt[NBK];
__device__ int           g_boff[NBK + 1];
__device__ int           g_bfill[NBK];
__device__ int           g_bsum[128];
__device__ int           g_flags[2];

// ---------------- tf32 round ----------------
__device__ __forceinline__ unsigned f2tf(float f) {
    unsigned r;
    asm("cvt.rna.tf32.f32 %0, %1;" : "=r"(r) : "f"(f));
    return r;
}

// ---------------- prep0: detect dtypes + zero + round weights ------------
__global__ void k_prep0(const unsigned* __restrict__ w, const unsigned char* __restrict__ mb,
                        const float* __restrict__ selfw, const float* __restrict__ relw) {
    if (blockIdx.x == 0) {
        __shared__ int s64, s32;
        if (threadIdx.x == 0) { s64 = 0; s32 = 0; }
        __syncthreads();
        if (threadIdx.x < 128) { if (w[2 * threadIdx.x + 1] != 0u) atomicAdd(&s64, 1); }
        if (threadIdx.x < 192) {
            int i = (threadIdx.x / 3) * 4 + 1 + (threadIdx.x % 3);
            if (mb[i] != 0) atomicAdd(&s32, 1);
        }
        __syncthreads();
        if (threadIdx.x == 0) { g_flags[0] = (s64 < 8); g_flags[1] = (s32 < 8); }
    }
    int stride = gridDim.x * blockDim.x;
    int g = blockIdx.x * blockDim.x + threadIdx.x;
    for (int i = g; i < N_REL * N_NODES; i += stride) g_deg[i] = 0;
    for (int i = g; i < NBK; i += stride) g_bcnt[i] = 0;
    for (int i = g; i < NW * CH * CH; i += stride) {
        float v = (i < CH * CH) ? selfw[i] : relw[i - CH * CH];
        g_B[i] = __uint_as_float(f2tf(v));
    }
}

__device__ __forceinline__ int rd_idx(const void* p, int i) {
    return g_flags[0] ? (int)((const long long*)p)[i] : ((const int*)p)[i];
}
__device__ __forceinline__ int rd_mask(const void* p, int i) {
    return g_flags[1] ? (((const int*)p)[i] != 0) : (int)((const unsigned char*)p)[i];
}

// ---------------- degree + bucket counting ----------------
__global__ void k_deg(const void* __restrict__ idx, const void* __restrict__ mask) {
    int e = blockIdx.x * blockDim.x + threadIdx.x;
    int rel = blockIdx.y;
    if (e >= N_EDGES) return;
    if (!rd_mask(mask, rel * N_EDGES + e)) return;
    int dst = rd_idx(idx, rel * 2 * N_EDGES + N_EDGES + e);
    atomicAdd(&g_deg[rel * N_NODES + dst], 1);
    int key = ((dst >> 6) * N_REL + rel) * 4 + ((dst >> 4) & 3);
    atomicAdd(&g_bcnt[key], 1);
}

// ---------------- scan stage 1 (+ invdeg piggybacked) ----------------
__global__ void k_scan1i() {
    __shared__ int sh[1024];
    int i = blockIdx.x * 1024 + threadIdx.x;
    int v = (i < NBK) ? g_bcnt[i] : 0;
    sh[threadIdx.x] = v;
    __syncthreads();
    for (int off = 1; off < 1024; off <<= 1) {
        int t = (threadIdx.x >= off) ? sh[threadIdx.x - off] : 0;
        __syncthreads();
        sh[threadIdx.x] += t;
        __syncthreads();
    }
    if (i < NBK) g_boff[i] = sh[threadIdx.x] - v;     // block-local exclusive
    if (threadIdx.x == 1023) g_bsum[blockIdx.x] = sh[1023];
    // invdeg (independent array; deg complete since k_deg finished)
    int stride = gridDim.x * blockDim.x;
    for (int j = blockIdx.x * 1024 + threadIdx.x; j < N_REL * N_NODES; j += stride) {
        int d = g_deg[j];
        g_invdeg[j] = d > 0 ? 1.0f / (float)d : 0.0f;
    }
}

// ---------------- scan stage 2+3 fused (redundant small top-scan) --------
__global__ void k_scan3b(int nb) {
    __shared__ int sb[128];
    if (threadIdx.x < 128) sb[threadIdx.x] = (threadIdx.x < nb) ? g_bsum[threadIdx.x] : 0;
    __syncthreads();
    int pref = 0;
    for (int j = 0; j < nb; j++) pref += (j < blockIdx.x) ? sb[j] : 0;
    int i = blockIdx.x * 1024 + threadIdx.x;
    if (i < NBK) {
        int o = g_boff[i] + pref;
        g_boff[i] = o;
        g_bfill[i] = o;
    }
    if (blockIdx.x == 0 && threadIdx.x == 0) {
        int tot = 0;
        for (int j = 0; j < nb; j++) tot += sb[j];
        g_boff[NBK] = tot;
    }
}

// ---------------- fill sorted edge meta ----------------
__global__ void k_fill(const void* __restrict__ idx, const void* __restrict__ mask) {
    int e = blockIdx.x * blockDim.x + threadIdx.x;
    int rel = blockIdx.y;
    if (e >= N_EDGES) return;
    if (!rd_mask(mask, rel * N_EDGES + e)) return;
    int src = rd_idx(idx, rel * 2 * N_EDGES + e);
    int dst = rd_idx(idx, rel * 2 * N_EDGES + N_EDGES + e);
    int key = ((dst >> 6) * N_REL + rel) * 4 + ((dst >> 4) & 3);
    int pos = atomicAdd(&g_bfill[key], 1);
    g_emeta[pos] = (unsigned)src | ((unsigned)(dst & 63) << 17);
}

// ---------------- fused kernel helpers ----------------
// load B fragments for one ks step straight from global (L2/L1-resident)
__device__ __forceinline__ void ldb(unsigned b[4][2], const float* __restrict__ Bw,
                                    int ks, int lane) {
    const float* p = Bw + (ks * 8 + (lane & 3)) * CH + (lane >> 2);
#pragma unroll
    for (int nf = 0; nf < 4; nf++) {
        b[nf][0] = __float_as_uint(__ldg(p + nf * 8));
        b[nf][1] = __float_as_uint(__ldg(p + nf * 8 + 4 * CH));
    }
}

// one ks-step of mma (a-frags from smem + cvt, b from regs) — R10 math
__device__ __forceinline__ void mma1(float (*c)[4][4], const float* Akt,
                                     const unsigned b[4][2], int ks, int lane) {
    unsigned a[4][4];
    int col = ks * 8 + (lane & 3);
    int r = lane >> 2;
#pragma unroll
    for (int mf = 0; mf < 4; mf++) {
        const float* Ap = Akt + (mf * 16 + r) * HS + col;
        a[mf][0] = f2tf(Ap[0]);
        a[mf][1] = f2tf(Ap[8 * HS]);
        a[mf][2] = f2tf(Ap[4]);
        a[mf][3] = f2tf(Ap[8 * HS + 4]);
    }
#pragma unroll
    for (int mf = 0; mf < 4; mf++)
#pragma unroll
        for (int nf = 0; nf < 4; nf++)
            asm volatile(
                "mma.sync.aligned.m16n8k8.row.col.f32.tf32.tf32.f32 "
                "{%0,%1,%2,%3},{%4,%5,%6,%7},{%8,%9},{%0,%1,%2,%3};\n"
                : "+f"(c[mf][nf][0]), "+f"(c[mf][nf][1]),
                  "+f"(c[mf][nf][2]), "+f"(c[mf][nf][3])
                : "r"(a[mf][0]), "r"(a[mf][1]), "r"(a[mf][2]), "r"(a[mf][3]),
                  "r"(b[nf][0]), "r"(b[nf][1]));
}

// gather warp gwid: rows [gwid*16, gwid*16+16) = sum x[src]*invdeg (R10 code)
__device__ __forceinline__ void gather_rel(const float* __restrict__ x, float* hb,
                                           int tile, int rel, int gwid, int lane) {
    float4 z = make_float4(0.f, 0.f, 0.f, 0.f);
    int r0 = gwid * 16;
#pragma unroll
    for (int r = 0; r < 16; r++)
        ((float4*)(hb + (r0 + r) * HS))[lane] = z;

    int key = (tile * N_REL + rel) * 4 + gwid;
    int beg = g_boff[key], end = g_boff[key + 1];
    const float* vd = g_invdeg + rel * N_NODES + tile * TM;
    for (int base = beg; base < end; base += 32) {
        unsigned m = 0;
        if (base + lane < end) m = g_emeta[base + lane];
        int n = min(32, end - base);
        int j = 0;
        for (; j + 4 <= n; j += 4) {                 // 4 independent 512B loads in flight
            int dl[4], sn[4];
            float sc[4];
            float4 v[4];
#pragma unroll
            for (int t = 0; t < 4; t++) {
                unsigned u = __shfl_sync(0xffffffffu, m, j + t);
                sn[t] = (int)(u & 0x1FFFFu);
                dl[t] = (int)(u >> 17);
            }
#pragma unroll
            for (int t = 0; t < 4; t++) sc[t] = __ldg(vd + dl[t]);
#pragma unroll
            for (int t = 0; t < 4; t++)
                v[t] = __ldg((const float4*)(x + (size_t)sn[t] * CH) + lane);
#pragma unroll
            for (int t = 0; t < 4; t++) {
                float4* hp = (float4*)(hb + dl[t] * HS) + lane;
                float4 hv = *hp;
                hv.x += v[t].x * sc[t]; hv.y += v[t].y * sc[t];
                hv.z += v[t].z * sc[t]; hv.w += v[t].w * sc[t];
                *hp = hv;
            }
        }
        for (; j < n; j++) {
            unsigned u = __shfl_sync(0xffffffffu, m, j);
            int sn = (int)(u & 0x1FFFFu);
            int dl = (int)(u >> 17);
            float s = __ldg(vd + dl);
            float4 v = __ldg((const float4*)(x + (size_t)sn * CH) + lane);
            float4* hp = (float4*)(hb + dl * HS) + lane;
            float4 hv = *hp;
            hv.x += v.x * s; hv.y += v.y * s; hv.z += v.z * s; hv.w += v.w * s;
            *hp = hv;
        }
    }
}

// ---------------- fused: 64-row tiles, warps 0-3 mma, 4-7 gather ---------
__global__ __launch_bounds__(256, 2) void k_fused(const float* __restrict__ x,
                                                  float* __restrict__ out) {
    extern __shared__ float sm[];
    float* hA = sm;                 // 2 buffers, only smem use
    int tid = threadIdx.x, wid = tid >> 5, lane = tid & 31;
    int tile = blockIdx.x, bM = tile * TM;
    bool is_mma = (wid < 4);

    float c[4][4][4];
#pragma unroll
    for (int i = 0; i < 4; i++)
#pragma unroll
        for (int j = 0; j < 4; j++)
#pragma unroll
            for (int k = 0; k < 4; k++) c[i][j][k] = 0.f;

    unsigned bfr[2][4][2];
    if (is_mma) {
        // prefetch (w=0, kt=0, ks=0)
        ldb(bfr[0], g_B + wid * 32, 0, lane);
    } else {
        // self tile (weight 0) = x rows -> hA[0]
        int gwid = wid - 4, r0 = gwid * 16;
#pragma unroll
        for (int r = 0; r < 16; r++) {
            int rg = bM + r0 + r;
            float4 v = make_float4(0.f, 0.f, 0.f, 0.f);
            if (rg < N_NODES) v = __ldg((const float4*)(x + (size_t)rg * CH) + lane);
            ((float4*)(hA + (r0 + r) * HS))[lane] = v;
        }
    }
    __syncthreads();   // hA[0] ready

#pragma unroll 1
    for (int w = 0; w < NW; w++) {
        if (is_mma) {
            const float* A = hA + (w & 1) * HSZ;
            const float* Bw = g_B + (size_t)w * CH * CH + wid * 32;
#pragma unroll 1
            for (int kt = 0; kt < 4; kt++) {
                const float* Akt = A + kt * 32;
#pragma unroll
                for (int ks = 0; ks < 4; ks++) {
                    int g = (w * 4 + kt) * 4 + ks;       // global ks counter
                    // prefetch next ks-step's B fragments
                    int nks = ks + 1, nkt = kt, nw = w;
                    if (nks == 4) { nks = 0; nkt++; if (nkt == 4) { nkt = 0; nw++; } }
                    if (nw < NW)
                        ldb(bfr[(g + 1) & 1],
                            g_B + (size_t)nw * CH * CH + nkt * 32 * CH + wid * 32,
                            nks, lane);
                    mma1(c, Akt, bfr[g & 1], ks, lane);
                }
            }
        } else if (w < NW - 1) {
            // build hA[(w+1)&1] for relation w while mma chews on hA[w&1]
            gather_rel(x, hA + ((w + 1) & 1) * HSZ, tile, w, wid - 4, lane);
        }
        __syncthreads();   // weight boundary: next A ready, current A free
    }

    // epilogue (mma warps own the accumulators)
    if (is_mma) {
        int wn = wid;
#pragma unroll
        for (int mf = 0; mf < 4; mf++) {
            int r0 = bM + mf * 16 + (lane >> 2);
#pragma unroll
            for (int nf = 0; nf < 4; nf++) {
                int cc = wn * 32 + nf * 8 + (lane & 3) * 2;
                if (r0 < N_NODES)
                    *(float2*)(out + (size_t)r0 * CH + cc) =
                        make_float2(c[mf][nf][0], c[mf][nf][1]);
                if (r0 + 8 < N_NODES)
                    *(float2*)(out + (size_t)(r0 + 8) * CH + cc) =
                        make_float2(c[mf][nf][2], c[mf][nf][3]);
            }
        }
    }
}

// ---------------- launch (6 total: k_fused is launch index 5 for ncu) ----
extern "C" void kernel_launch(void* const* d_in, const int* in_sizes, int n_in,
                              void* d_out, int out_size) {
    const float* x     = (const float*)d_in[0];
    const void*  idx   = d_in[1];
    const void*  mask  = d_in[2];
    const float* selfw = (const float*)d_in[3];
    const float* relw  = (const float*)d_in[4];
    float* out = (float*)d_out;

    static int init = 0;
    size_t smem = SMEM_FLOATS * sizeof(float);   // 67584 B
    if (!init) {
        cudaFuncSetAttribute(k_fused, cudaFuncAttributeMaxDynamicSharedMemorySize, (int)smem);
        init = 1;
    }

    int nb1 = (NBK + 1023) / 1024;   // 98

    k_prep0<<<4096, 256>>>((const unsigned*)idx, (const unsigned char*)mask, selfw, relw);
    k_deg<<<dim3((N_EDGES + 255) / 256, N_REL), 256>>>(idx, mask);
    k_scan1i<<<nb1, 1024>>>();
    k_scan3b<<<nb1, 1024>>>(nb1);
    k_fill<<<dim3((N_EDGES + 255) / 256, N_REL), 256>>>(idx, mask);
    k_fused<<<NT, 256, smem>>>(x, out);
}

// round 14
// speedup vs baseline: 1.0749x; 1.0749x over previous
#include <cuda_runtime.h>
#include <cstdint>

#define N_NODES 100000
#define CH      128
#define N_REL   16
#define N_EDGES 200000
#define NW      17                        /* self + 16 relations */
#define TM      64                        /* tile rows */
#define NT      ((N_NODES + TM - 1) / TM) /* 1563 dst tiles */
#define NBK     (NT * N_REL * 4)          /* 100032 buckets (tile,rel,gwarp) */
#define HS      132                       /* hA row stride (floats) */
#define BS      136                       /* B smem row stride (floats) */
#define HSZ     (TM * HS)                 /* 8448 floats per hA buffer */

// smem: hA0 | hA1 | B-ring(2 x 32*BS)
#define SMF_B    (2 * HSZ)
#define SMEM_FLOATS (SMF_B + 2 * 32 * BS)  /* 25600 floats = 102400 B -> 2 CTA/SM */
#define NSTG     (4 * NW)                 /* 68 B k-chunks */
#define NSB      98                       /* scan blocks */

// ---------------- device scratch (zero-init at load; self-cleaning) ------
__device__ unsigned      g_emeta[N_REL * N_EDGES];   // src | dl<<17 (sorted by bucket)
__device__ float         g_B[NW * CH * CH];          // tf32-rounded weights
__device__ int           g_deg[N_REL * N_NODES];     // zeroed by k_scanall after use
__device__ float         g_invdeg[N_REL * N_NODES];
__device__ int           g_bcnt[NBK];                // zeroed by k_scanall after use
__device__ int           g_boff[NBK + 1];
__device__ int           g_bfill[NBK];
__device__ int           g_bsum[NSB];
__device__ int           g_sflag[128];               // zeroed by k_fill2 after use

// ---------------- tf32 round ----------------
__device__ __forceinline__ unsigned f2tf(float f) {
    unsigned r;
    asm("cvt.rna.tf32.f32 %0, %1;" : "=r"(r) : "f"(f));
    return r;
}

// per-block dtype detection (jax int64/bool layout may vary); 256-thread blocks
__device__ __forceinline__ void detect_flags(const void* idx, const void* mask,
                                             bool& f64, bool& fm32) {
    __shared__ int s64, s32;
    if (threadIdx.x == 0) { s64 = 0; s32 = 0; }
    __syncthreads();
    const unsigned* w = (const unsigned*)idx;
    const unsigned char* mb = (const unsigned char*)mask;
    if (threadIdx.x < 128) { if (w[2 * threadIdx.x + 1] != 0u) atomicAdd(&s64, 1); }
    if (threadIdx.x < 192) {
        int i = (threadIdx.x / 3) * 4 + 1 + (threadIdx.x % 3);
        if (mb[i] != 0) atomicAdd(&s32, 1);
    }
    __syncthreads();
    f64 = (s64 < 8);
    fm32 = (s32 < 8);
}

__device__ __forceinline__ int rd_idx2(const void* p, long long i, bool f64) {
    return f64 ? (int)((const long long*)p)[i] : ((const int*)p)[i];
}
__device__ __forceinline__ int rd_mask2(const void* p, int i, bool fm32) {
    return fm32 ? (((const int*)p)[i] != 0) : (int)((const unsigned char*)p)[i];
}

// ---------------- L0: degree + bucket counting + weight rounding ---------
__global__ void k_deg2(const void* __restrict__ idx, const void* __restrict__ mask,
                       const float* __restrict__ selfw, const float* __restrict__ relw) {
    bool f64, fm32;
    detect_flags(idx, mask, f64, fm32);

    // roundB piggyback (flattened 2D grid id; 3.2M threads cover 278K elements)
    long long gid = ((long long)(blockIdx.y * gridDim.x + blockIdx.x)) * blockDim.x
                    + threadIdx.x;
    if (gid < (long long)NW * CH * CH) {
        int i = (int)gid;
        float v = (i < CH * CH) ? selfw[i] : relw[i - CH * CH];
        g_B[i] = __uint_as_float(f2tf(v));
    }

    int e = blockIdx.x * blockDim.x + threadIdx.x;
    int rel = blockIdx.y;
    if (e >= N_EDGES) return;
    if (!rd_mask2(mask, rel * N_EDGES + e, fm32)) return;
    int dst = rd_idx2(idx, (long long)rel * 2 * N_EDGES + N_EDGES + e, f64);
    atomicAdd(&g_deg[rel * N_NODES + dst], 1);
    int key = ((dst >> 6) * N_REL + rel) * 4 + ((dst >> 4) & 3);
    atomicAdd(&g_bcnt[key], 1);
}

// ---------------- L1: single-launch scan (aggregate lookback) + invdeg ---
__global__ void k_scanall() {
    __shared__ int sh[1024];
    __shared__ int spref;
    int b = blockIdx.x;
    int i = b * 1024 + threadIdx.x;
    int v = (i < NBK) ? g_bcnt[i] : 0;
    sh[threadIdx.x] = v;
    __syncthreads();
    for (int off = 1; off < 1024; off <<= 1) {
        int t = (threadIdx.x >= off) ? sh[threadIdx.x - off] : 0;
        __syncthreads();
        sh[threadIdx.x] += t;
        __syncthreads();
    }
    int excl = sh[threadIdx.x] - v;   // block-local exclusive

    if (threadIdx.x == 1023) {
        g_bsum[b] = sh[1023];
        __threadfence();
        atomicExch(&g_sflag[b], 1);
    }
    if (threadIdx.x == 0) {
        int p = 0;
        for (int j = 0; j < b; j++) {
            while (atomicAdd(&g_sflag[j], 0) == 0) { }
            p += g_bsum[j];
        }
        spref = p;
    }
    __syncthreads();

    if (i < NBK) {
        int o = excl + spref;
        g_boff[i] = o;
        g_bfill[i] = o;
        g_bcnt[i] = 0;                         // self-clean for next replay
    }
    if (b == NSB - 1 && threadIdx.x == 1023)
        g_boff[NBK] = spref + sh[1023];        // total

    // invdeg + self-clean g_deg
    for (int j = i; j < N_REL * N_NODES; j += NSB * 1024) {
        int d = g_deg[j];
        g_invdeg[j] = d > 0 ? 1.0f / (float)d : 0.0f;
        g_deg[j] = 0;
    }
}

// ---------------- L2: fill sorted edge meta (+ zero scan flags) ----------
__global__ void k_fill2(const void* __restrict__ idx, const void* __restrict__ mask) {
    bool f64, fm32;
    detect_flags(idx, mask, f64, fm32);
    if (blockIdx.x == 0 && blockIdx.y == 0 && threadIdx.x < 128)
        g_sflag[threadIdx.x] = 0;              // self-clean for next replay
    int e = blockIdx.x * blockDim.x + threadIdx.x;
    int rel = blockIdx.y;
    if (e >= N_EDGES) return;
    if (!rd_mask2(mask, rel * N_EDGES + e, fm32)) return;
    int src = rd_idx2(idx, (long long)rel * 2 * N_EDGES + e, f64);
    int dst = rd_idx2(idx, (long long)rel * 2 * N_EDGES + N_EDGES + e, f64);
    int key = ((dst >> 6) * N_REL + rel) * 4 + ((dst >> 4) & 3);
    int pos = atomicAdd(&g_bfill[key], 1);
    g_emeta[pos] = (unsigned)src | ((unsigned)(dst & 63) << 17);
}

// ---------------- fused kernel helpers (identical to R10) ----------------
__device__ __forceinline__ void cp16(float* sdst, const float* gsrc) {
    unsigned s = (unsigned)__cvta_generic_to_shared(sdst);
    asm volatile("cp.async.cg.shared.global [%0], [%1], 16;\n" :: "r"(s), "l"(gsrc));
}

// B stage s (weight s>>2, k-chunk s&3) into ring slot s&1. mma threads (tid 0..127).
__device__ __forceinline__ void cp_stage(float* sB, int s, int tid) {
    if (s < NSTG) {
        int w = s >> 2, kt = s & 3;
        float* dB = sB + (s & 1) * 32 * BS;
        const float* src0 = g_B + (size_t)w * CH * CH + kt * 32 * CH;
#pragma unroll
        for (int i = 0; i < 8; i++) {
            int idx = tid + 128 * i;
            int kr = idx >> 5, c4 = idx & 31;
            cp16(dB + kr * BS + c4 * 4, src0 + kr * CH + c4 * 4);
        }
    }
    asm volatile("cp.async.commit_group;\n");   // uniform group count
}

__device__ __forceinline__ void mma4(float (*c)[4][4], const float* A, const float* Bsm,
                                     int lane) {
#pragma unroll
    for (int ks = 0; ks < 4; ks++) {
        unsigned a[4][4], b[4][2];
        int col = ks * 8 + (lane & 3);
        int r = lane >> 2;
#pragma unroll
        for (int mf = 0; mf < 4; mf++) {
            const float* Ap = A + (mf * 16 + r) * HS + col;
            a[mf][0] = f2tf(Ap[0]);
            a[mf][1] = f2tf(Ap[8 * HS]);
            a[mf][2] = f2tf(Ap[4]);
            a[mf][3] = f2tf(Ap[8 * HS + 4]);
        }
        int kr = ks * 8 + (lane & 3);
#pragma unroll
        for (int nf = 0; nf < 4; nf++) {
            const float* Bp = Bsm + kr * BS + nf * 8 + (lane >> 2);
            b[nf][0] = __float_as_uint(Bp[0]);       // pre-rounded tf32
            b[nf][1] = __float_as_uint(Bp[4 * BS]);
        }
#pragma unroll
        for (int mf = 0; mf < 4; mf++)
#pragma unroll
            for (int nf = 0; nf < 4; nf++)
                asm volatile(
                    "mma.sync.aligned.m16n8k8.row.col.f32.tf32.tf32.f32 "
                    "{%0,%1,%2,%3},{%4,%5,%6,%7},{%8,%9},{%0,%1,%2,%3};\n"
                    : "+f"(c[mf][nf][0]), "+f"(c[mf][nf][1]),
                      "+f"(c[mf][nf][2]), "+f"(c[mf][nf][3])
                    : "r"(a[mf][0]), "r"(a[mf][1]), "r"(a[mf][2]), "r"(a[mf][3]),
                      "r"(b[nf][0]), "r"(b[nf][1]));
    }
}

// gather warp gwid: rows [gwid*16, gwid*16+16) = sum x[src]*invdeg (R10 code)
__device__ __forceinline__ void gather_rel(const float* __restrict__ x, float* hb,
                                           int tile, int rel, int gwid, int lane) {
    float4 z = make_float4(0.f, 0.f, 0.f, 0.f);
    int r0 = gwid * 16;
#pragma unroll
    for (int r = 0; r < 16; r++)
        ((float4*)(hb + (r0 + r) * HS))[lane] = z;

    int key = (tile * N_REL + rel) * 4 + gwid;
    int beg = g_boff[key], end = g_boff[key + 1];
    const float* vd = g_invdeg + rel * N_NODES + tile * TM;
    for (int base = beg; base < end; base += 32) {
        unsigned m = 0;
        if (base + lane < end) m = g_emeta[base + lane];
        int n = min(32, end - base);
        int j = 0;
        for (; j + 4 <= n; j += 4) {                 // 4 independent 512B loads in flight
            int dl[4], sn[4];
            float sc[4];
            float4 v[4];
#pragma unroll
            for (int t = 0; t < 4; t++) {
                unsigned u = __shfl_sync(0xffffffffu, m, j + t);
                sn[t] = (int)(u & 0x1FFFFu);
                dl[t] = (int)(u >> 17);
            }
#pragma unroll
            for (int t = 0; t < 4; t++) sc[t] = __ldg(vd + dl[t]);
#pragma unroll
            for (int t = 0; t < 4; t++)
                v[t] = __ldg((const float4*)(x + (size_t)sn[t] * CH) + lane);
#pragma unroll
            for (int t = 0; t < 4; t++) {
                float4* hp = (float4*)(hb + dl[t] * HS) + lane;
                float4 hv = *hp;
                hv.x += v[t].x * sc[t]; hv.y += v[t].y * sc[t];
                hv.z += v[t].z * sc[t]; hv.w += v[t].w * sc[t];
                *hp = hv;
            }
        }
        for (; j < n; j++) {
            unsigned u = __shfl_sync(0xffffffffu, m, j);
            int sn = (int)(u & 0x1FFFFu);
            int dl = (int)(u >> 17);
            float s = __ldg(vd + dl);
            float4 v = __ldg((const float4*)(x + (size_t)sn * CH) + lane);
            float4* hp = (float4*)(hb + dl * HS) + lane;
            float4 hv = *hp;
            hv.x += v.x * s; hv.y += v.y * s; hv.z += v.z * s; hv.w += v.w * s;
            *hp = hv;
        }
    }
}

// ---------------- fused: 64-row tiles, warps 0-3 mma, 4-7 gather, 2 CTA/SM
__global__ __launch_bounds__(256, 2) void k_fused(const float* __restrict__ x,
                                                  float* __restrict__ out) {
    extern __shared__ float sm[];
    float* hA = sm;                 // 2 buffers
    float* sB = sm + SMF_B;         // 2-slot ring
    int tid = threadIdx.x, wid = tid >> 5, lane = tid & 31;
    int tile = blockIdx.x, bM = tile * TM;
    bool is_mma = (wid < 4);

    float c[4][4][4];
#pragma unroll
    for (int i = 0; i < 4; i++)
#pragma unroll
        for (int j = 0; j < 4; j++)
#pragma unroll
            for (int k = 0; k < 4; k++) c[i][j][k] = 0.f;

    if (is_mma) {
        cp_stage(sB, 0, tid);       // preload stage 0
    } else {
        // self tile (weight 0) = x rows -> hA[0]
        int gwid = wid - 4, r0 = gwid * 16;
#pragma unroll
        for (int r = 0; r < 16; r++) {
            int rg = bM + r0 + r;
            float4 v = make_float4(0.f, 0.f, 0.f, 0.f);
            if (rg < N_NODES) v = __ldg((const float4*)(x + (size_t)rg * CH) + lane);
            ((float4*)(hA + (r0 + r) * HS))[lane] = v;
        }
    }
    __syncthreads();   // hA[0] ready

#pragma unroll 1
    for (int w = 0; w < NW; w++) {
        if (is_mma) {
            int wn = wid;                          // 1x4 warp grid over 64x128
            const float* A = hA + (w & 1) * HSZ;
#pragma unroll 1
            for (int kt = 0; kt < 4; kt++) {
                int s = w * 4 + kt;
                asm volatile("cp.async.wait_group 0;\n");         // stage s landed
                asm volatile("bar.sync 1, 128;\n" ::: "memory");  // mma copies/reads done
                cp_stage(sB, s + 1, tid);          // slot (s+1)&1: readers done at bar
                mma4(c, A + kt * 32, sB + (s & 1) * 32 * BS + wn * 32, lane);
            }
        } else if (w < NW - 1) {
            // build hA[(w+1)&1] for relation w while mma chews on hA[w&1]
            gather_rel(x, hA + ((w + 1) & 1) * HSZ, tile, w, wid - 4, lane);
        }
        __syncthreads();   // weight boundary: next A ready, current A free
    }

    // epilogue (mma warps own the accumulators)
    if (is_mma) {
        int wn = wid;
#pragma unroll
        for (int mf = 0; mf < 4; mf++) {
            int r0 = bM + mf * 16 + (lane >> 2);
#pragma unroll
            for (int nf = 0; nf < 4; nf++) {
                int cc = wn * 32 + nf * 8 + (lane & 3) * 2;
                if (r0 < N_NODES)
                    *(float2*)(out + (size_t)r0 * CH + cc) =
                        make_float2(c[mf][nf][0], c[mf][nf][1]);
                if (r0 + 8 < N_NODES)
                    *(float2*)(out + (size_t)(r0 + 8) * CH + cc) =
                        make_float2(c[mf][nf][2], c[mf][nf][3]);
            }
        }
    }
}

// ---------------- launch: deg(0) scanall(1) fill(2) fused(3) -------------
extern "C" void kernel_launch(void* const* d_in, const int* in_sizes, int n_in,
                              void* d_out, int out_size) {
    const float* x     = (const float*)d_in[0];
    const void*  idx   = d_in[1];
    const void*  mask  = d_in[2];
    const float* selfw = (const float*)d_in[3];
    const float* relw  = (const float*)d_in[4];
    float* out = (float*)d_out;

    static int init = 0;
    size_t smem = SMEM_FLOATS * sizeof(float);   // 102400 B
    if (!init) {
        cudaFuncSetAttribute(k_fused, cudaFuncAttributeMaxDynamicSharedMemorySize, (int)smem);
        init = 1;
    }

    k_deg2<<<dim3((N_EDGES + 255) / 256, N_REL), 256>>>(idx, mask, selfw, relw);
    k_scanall<<<NSB, 1024>>>();
    k_fill2<<<dim3((N_EDGES + 255) / 256, N_REL), 256>>>(idx, mask);
    k_fused<<<NT, 256, smem>>>(x, out);
}

// round 15
// speedup vs baseline: 1.1950x; 1.1118x over previous
#include <cuda_runtime.h>
#include <cstdint>

#define N_NODES 100000
#define CH      128
#define N_REL   16
#define N_EDGES 200000
#define NW      17                        /* self + 16 relations */
#define TM      64                        /* tile rows */
#define NT      ((N_NODES + TM - 1) / TM) /* 1563 dst tiles */
#define NBK     (NT * N_REL * 4)          /* 100032 buckets (tile,rel,gwarp) */
#define HS      132                       /* hA row stride (floats) */
#define BS      136                       /* B smem row stride (floats) */
#define HSZ     (TM * HS)                 /* 8448 floats per hA buffer */

// smem: hA0 | hA1 | B-ring(2 x 32*BS)
#define SMF_B    (2 * HSZ)
#define SMEM_FLOATS (SMF_B + 2 * 32 * BS)  /* 25600 floats = 102400 B -> 2 CTA/SM */
#define NSTG     (4 * NW)                 /* 68 B k-chunks */
#define NSB      98                       /* scan blocks */

// ---------------- device scratch (zero-init at load; self-cleaning) ------
__device__ unsigned      g_emeta[N_REL * N_EDGES];   // src | dl<<17 (sorted by bucket)
__device__ float         g_B[NW * CH * CH];          // tf32-rounded weights
__device__ int           g_deg[N_REL * N_NODES];     // zeroed by k_scanall after use
__device__ float         g_invdeg[N_REL * N_NODES];
__device__ int           g_bcnt[NBK];                // zeroed by k_scanall after use
__device__ int           g_boff[NBK + 1];
__device__ int           g_bfill[NBK];
__device__ int           g_bsum[NSB];
__device__ int           g_sflag[128];               // zeroed by k_fill2 after use

// ---------------- tf32 round ----------------
__device__ __forceinline__ unsigned f2tf(float f) {
    unsigned r;
    asm("cvt.rna.tf32.f32 %0, %1;" : "=r"(r) : "f"(f));
    return r;
}

// per-block dtype detection (jax int64/bool layout may vary); 256-thread blocks
__device__ __forceinline__ void detect_flags(const void* idx, const void* mask,
                                             bool& f64, bool& fm32) {
    __shared__ int s64, s32;
    if (threadIdx.x == 0) { s64 = 0; s32 = 0; }
    __syncthreads();
    const unsigned* w = (const unsigned*)idx;
    const unsigned char* mb = (const unsigned char*)mask;
    if (threadIdx.x < 128) { if (w[2 * threadIdx.x + 1] != 0u) atomicAdd(&s64, 1); }
    if (threadIdx.x < 192) {
        int i = (threadIdx.x / 3) * 4 + 1 + (threadIdx.x % 3);
        if (mb[i] != 0) atomicAdd(&s32, 1);
    }
    __syncthreads();
    f64 = (s64 < 8);
    fm32 = (s32 < 8);
}

__device__ __forceinline__ int rd_idx2(const void* p, long long i, bool f64) {
    return f64 ? (int)((const long long*)p)[i] : ((const int*)p)[i];
}
__device__ __forceinline__ int rd_mask2(const void* p, int i, bool fm32) {
    return fm32 ? (((const int*)p)[i] != 0) : (int)((const unsigned char*)p)[i];
}

// ---------------- L0: degree + bucket counting + weight rounding ---------
__global__ void k_deg2(const void* __restrict__ idx, const void* __restrict__ mask,
                       const float* __restrict__ selfw, const float* __restrict__ relw) {
    bool f64, fm32;
    detect_flags(idx, mask, f64, fm32);

    long long gid = ((long long)(blockIdx.y * gridDim.x + blockIdx.x)) * blockDim.x
                    + threadIdx.x;
    if (gid < (long long)NW * CH * CH) {
        int i = (int)gid;
        float v = (i < CH * CH) ? selfw[i] : relw[i - CH * CH];
        g_B[i] = __uint_as_float(f2tf(v));
    }

    int e = blockIdx.x * blockDim.x + threadIdx.x;
    int rel = blockIdx.y;
    if (e >= N_EDGES) return;
    if (!rd_mask2(mask, rel * N_EDGES + e, fm32)) return;
    int dst = rd_idx2(idx, (long long)rel * 2 * N_EDGES + N_EDGES + e, f64);
    atomicAdd(&g_deg[rel * N_NODES + dst], 1);
    int key = ((dst >> 6) * N_REL + rel) * 4 + ((dst >> 4) & 3);
    atomicAdd(&g_bcnt[key], 1);
}

// ---------------- L1: single-launch scan (PARALLEL lookback) + invdeg ----
__global__ void k_scanall() {
    __shared__ int sh[1024];
    __shared__ int sred[128];
    int b = blockIdx.x;
    int i = b * 1024 + threadIdx.x;
    int v = (i < NBK) ? g_bcnt[i] : 0;
    sh[threadIdx.x] = v;
    __syncthreads();
    for (int off = 1; off < 1024; off <<= 1) {
        int t = (threadIdx.x >= off) ? sh[threadIdx.x - off] : 0;
        __syncthreads();
        sh[threadIdx.x] += t;
        __syncthreads();
    }
    int excl = sh[threadIdx.x] - v;   // block-local exclusive

    if (threadIdx.x == 1023) {
        g_bsum[b] = sh[1023];
        __threadfence();
        atomicExch(&g_sflag[b], 1);
    }
    // parallel lookback: thread t (<b) polls flag t, then tree-reduce
    if (threadIdx.x < 128) {
        int part = 0;
        if ((int)threadIdx.x < b) {
            while (atomicAdd(&g_sflag[threadIdx.x], 0) == 0) { }
            part = g_bsum[threadIdx.x];
        }
        sred[threadIdx.x] = part;
    }
    __syncthreads();
    for (int off = 64; off > 0; off >>= 1) {
        if (threadIdx.x < (unsigned)off) sred[threadIdx.x] += sred[threadIdx.x + off];
        __syncthreads();
    }
    int spref = sred[0];

    if (i < NBK) {
        int o = excl + spref;
        g_boff[i] = o;
        g_bfill[i] = o;
        g_bcnt[i] = 0;                         // self-clean for next replay
    }
    if (b == NSB - 1 && threadIdx.x == 1023)
        g_boff[NBK] = spref + sh[1023];        // total

    // invdeg + self-clean g_deg
    for (int j = i; j < N_REL * N_NODES; j += NSB * 1024) {
        int d = g_deg[j];
        g_invdeg[j] = d > 0 ? 1.0f / (float)d : 0.0f;
        g_deg[j] = 0;
    }
}

// ---------------- L2: fill sorted edge meta (+ zero scan flags) ----------
__global__ void k_fill2(const void* __restrict__ idx, const void* __restrict__ mask) {
    bool f64, fm32;
    detect_flags(idx, mask, f64, fm32);
    if (blockIdx.x == 0 && blockIdx.y == 0 && threadIdx.x < 128)
        g_sflag[threadIdx.x] = 0;              // self-clean for next replay
    int e = blockIdx.x * blockDim.x + threadIdx.x;
    int rel = blockIdx.y;
    if (e >= N_EDGES) return;
    if (!rd_mask2(mask, rel * N_EDGES + e, fm32)) return;
    int src = rd_idx2(idx, (long long)rel * 2 * N_EDGES + e, f64);
    int dst = rd_idx2(idx, (long long)rel * 2 * N_EDGES + N_EDGES + e, f64);
    int key = ((dst >> 6) * N_REL + rel) * 4 + ((dst >> 4) & 3);
    int pos = atomicAdd(&g_bfill[key], 1);
    g_emeta[pos] = (unsigned)src | ((unsigned)(dst & 63) << 17);
}

// ---------------- fused kernel helpers (identical to R10) ----------------
__device__ __forceinline__ void cp16(float* sdst, const float* gsrc) {
    unsigned s = (unsigned)__cvta_generic_to_shared(sdst);
    asm volatile("cp.async.cg.shared.global [%0], [%1], 16;\n" :: "r"(s), "l"(gsrc));
}

__device__ __forceinline__ void cp_stage(float* sB, int s, int tid) {
    if (s < NSTG) {
        int w = s >> 2, kt = s & 3;
        float* dB = sB + (s & 1) * 32 * BS;
        const float* src0 = g_B + (size_t)w * CH * CH + kt * 32 * CH;
#pragma unroll
        for (int i = 0; i < 8; i++) {
            int idx = tid + 128 * i;
            int kr = idx >> 5, c4 = idx & 31;
            cp16(dB + kr * BS + c4 * 4, src0 + kr * CH + c4 * 4);
        }
    }
    asm volatile("cp.async.commit_group;\n");   // uniform group count
}

__device__ __forceinline__ void mma4(float (*c)[4][4], const float* A, const float* Bsm,
                                     int lane) {
#pragma unroll
    for (int ks = 0; ks < 4; ks++) {
        unsigned a[4][4], b[4][2];
        int col = ks * 8 + (lane & 3);
        int r = lane >> 2;
#pragma unroll
        for (int mf = 0; mf < 4; mf++) {
            const float* Ap = A + (mf * 16 + r) * HS + col;
            a[mf][0] = f2tf(Ap[0]);
            a[mf][1] = f2tf(Ap[8 * HS]);
            a[mf][2] = f2tf(Ap[4]);
            a[mf][3] = f2tf(Ap[8 * HS + 4]);
        }
        int kr = ks * 8 + (lane & 3);
#pragma unroll
        for (int nf = 0; nf < 4; nf++) {
            const float* Bp = Bsm + kr * BS + nf * 8 + (lane >> 2);
            b[nf][0] = __float_as_uint(Bp[0]);       // pre-rounded tf32
            b[nf][1] = __float_as_uint(Bp[4 * BS]);
        }
#pragma unroll
        for (int mf = 0; mf < 4; mf++)
#pragma unroll
            for (int nf = 0; nf < 4; nf++)
                asm volatile(
                    "mma.sync.aligned.m16n8k8.row.col.f32.tf32.tf32.f32 "
                    "{%0,%1,%2,%3},{%4,%5,%6,%7},{%8,%9},{%0,%1,%2,%3};\n"
                    : "+f"(c[mf][nf][0]), "+f"(c[mf][nf][1]),
                      "+f"(c[mf][nf][2]), "+f"(c[mf][nf][3])
                    : "r"(a[mf][0]), "r"(a[mf][1]), "r"(a[mf][2]), "r"(a[mf][3]),
                      "r"(b[nf][0]), "r"(b[nf][1]));
    }
}

// gather warp gwid: rows [gwid*16, gwid*16+16) = sum x[src]*invdeg.
// MLP-8 batches (was 4): halves the serial L2 round-trip count.
__device__ __forceinline__ void gather_rel(const float* __restrict__ x, float* hb,
                                           int tile, int rel, int gwid, int lane) {
    float4 z = make_float4(0.f, 0.f, 0.f, 0.f);
    int r0 = gwid * 16;
#pragma unroll
    for (int r = 0; r < 16; r++)
        ((float4*)(hb + (r0 + r) * HS))[lane] = z;

    int key = (tile * N_REL + rel) * 4 + gwid;
    int beg = g_boff[key], end = g_boff[key + 1];
    const float* vd = g_invdeg + rel * N_NODES + tile * TM;
    for (int base = beg; base < end; base += 32) {
        unsigned m = 0;
        if (base + lane < end) m = g_emeta[base + lane];
        int n = min(32, end - base);
        int j = 0;
        for (; j + 8 <= n; j += 8) {                 // 8 independent 512B loads in flight
            int dl[8], sn[8];
            float sc[8];
            float4 v[8];
#pragma unroll
            for (int t = 0; t < 8; t++) {
                unsigned u = __shfl_sync(0xffffffffu, m, j + t);
                sn[t] = (int)(u & 0x1FFFFu);
                dl[t] = (int)(u >> 17);
            }
#pragma unroll
            for (int t = 0; t < 8; t++) sc[t] = __ldg(vd + dl[t]);
#pragma unroll
            for (int t = 0; t < 8; t++)
                v[t] = __ldg((const float4*)(x + (size_t)sn[t] * CH) + lane);
#pragma unroll
            for (int t = 0; t < 8; t++) {
                float4* hp = (float4*)(hb + dl[t] * HS) + lane;
                float4 hv = *hp;
                hv.x += v[t].x * sc[t]; hv.y += v[t].y * sc[t];
                hv.z += v[t].z * sc[t]; hv.w += v[t].w * sc[t];
                *hp = hv;
            }
        }
        for (; j + 4 <= n; j += 4) {                 // 4-batch tail
            int dl[4], sn[4];
            float sc[4];
            float4 v[4];
#pragma unroll
            for (int t = 0; t < 4; t++) {
                unsigned u = __shfl_sync(0xffffffffu, m, j + t);
                sn[t] = (int)(u & 0x1FFFFu);
                dl[t] = (int)(u >> 17);
            }
#pragma unroll
            for (int t = 0; t < 4; t++) sc[t] = __ldg(vd + dl[t]);
#pragma unroll
            for (int t = 0; t < 4; t++)
                v[t] = __ldg((const float4*)(x + (size_t)sn[t] * CH) + lane);
#pragma unroll
            for (int t = 0; t < 4; t++) {
                float4* hp = (float4*)(hb + dl[t] * HS) + lane;
                float4 hv = *hp;
                hv.x += v[t].x * sc[t]; hv.y += v[t].y * sc[t];
                hv.z += v[t].z * sc[t]; hv.w += v[t].w * sc[t];
                *hp = hv;
            }
        }
        for (; j < n; j++) {
            unsigned u = __shfl_sync(0xffffffffu, m, j);
            int sn = (int)(u & 0x1FFFFu);
            int dl = (int)(u >> 17);
            float s = __ldg(vd + dl);
            float4 v = __ldg((const float4*)(x + (size_t)sn * CH) + lane);
            float4* hp = (float4*)(hb + dl * HS) + lane;
            float4 hv = *hp;
            hv.x += v.x * s; hv.y += v.y * s; hv.z += v.z * s; hv.w += v.w * s;
            *hp = hv;
        }
    }
}

// ---------------- fused: 64-row tiles, warps 0-3 mma, 4-7 gather, 2 CTA/SM
__global__ __launch_bounds__(256, 2) void k_fused(const float* __restrict__ x,
                                                  float* __restrict__ out) {
    extern __shared__ float sm[];
    float* hA = sm;                 // 2 buffers
    float* sB = sm + SMF_B;         // 2-slot ring
    int tid = threadIdx.x, wid = tid >> 5, lane = tid & 31;
    int tile = blockIdx.x, bM = tile * TM;
    bool is_mma = (wid < 4);

    float c[4][4][4];
#pragma unroll
    for (int i = 0; i < 4; i++)
#pragma unroll
        for (int j = 0; j < 4; j++)
#pragma unroll
            for (int k = 0; k < 4; k++) c[i][j][k] = 0.f;

    if (is_mma) {
        cp_stage(sB, 0, tid);       // preload stage 0
    } else {
        // self tile (weight 0) = x rows -> hA[0]
        int gwid = wid - 4, r0 = gwid * 16;
#pragma unroll
        for (int r = 0; r < 16; r++) {
            int rg = bM + r0 + r;
            float4 v = make_float4(0.f, 0.f, 0.f, 0.f);
            if (rg < N_NODES) v = __ldg((const float4*)(x + (size_t)rg * CH) + lane);
            ((float4*)(hA + (r0 + r) * HS))[lane] = v;
        }
    }
    __syncthreads();   // hA[0] ready

#pragma unroll 1
    for (int w = 0; w < NW; w++) {
        if (is_mma) {
            int wn = wid;                          // 1x4 warp grid over 64x128
            const float* A = hA + (w & 1) * HSZ;
#pragma unroll 1
            for (int kt = 0; kt < 4; kt++) {
                int s = w * 4 + kt;
                asm volatile("cp.async.wait_group 0;\n");         // stage s landed
                asm volatile("bar.sync 1, 128;\n" ::: "memory");  // mma copies/reads done
                cp_stage(sB, s + 1, tid);          // slot (s+1)&1: readers done at bar
                mma4(c, A + kt * 32, sB + (s & 1) * 32 * BS + wn * 32, lane);
            }
        } else if (w < NW - 1) {
            // build hA[(w+1)&1] for relation w while mma chews on hA[w&1]
            gather_rel(x, hA + ((w + 1) & 1) * HSZ, tile, w, wid - 4, lane);
        }
        __syncthreads();   // weight boundary: next A ready, current A free
    }

    // epilogue (mma warps own the accumulators)
    if (is_mma) {
        int wn = wid;
#pragma unroll
        for (int mf = 0; mf < 4; mf++) {
            int r0 = bM + mf * 16 + (lane >> 2);
#pragma unroll
            for (int nf = 0; nf < 4; nf++) {
                int cc = wn * 32 + nf * 8 + (lane & 3) * 2;
                if (r0 < N_NODES)
                    *(float2*)(out + (size_t)r0 * CH + cc) =
                        make_float2(c[mf][nf][0], c[mf][nf][1]);
                if (r0 + 8 < N_NODES)
                    *(float2*)(out + (size_t)(r0 + 8) * CH + cc) =
                        make_float2(c[mf][nf][2], c[mf][nf][3]);
            }
        }
    }
}

// ---------------- launch: deg(0) scanall(1) fill(2) fused(3) -------------
extern "C" void kernel_launch(void* const* d_in, const int* in_sizes, int n_in,
                              void* d_out, int out_size) {
    const float* x     = (const float*)d_in[0];
    const void*  idx   = d_in[1];
    const void*  mask  = d_in[2];
    const float* selfw = (const float*)d_in[3];
    const float* relw  = (const float*)d_in[4];
    float* out = (float*)d_out;

    static int init = 0;
    size_t smem = SMEM_FLOATS * sizeof(float);   // 102400 B
    if (!init) {
        cudaFuncSetAttribute(k_fused, cudaFuncAttributeMaxDynamicSharedMemorySize, (int)smem);
        init = 1;
    }

    k_deg2<<<dim3((N_EDGES + 255) / 256, N_REL), 256>>>(idx, mask, selfw, relw);
    k_scanall<<<NSB, 1024>>>();
    k_fill2<<<dim3((N_EDGES + 255) / 256, N_REL), 256>>>(idx, mask);
    k_fused<<<NT, 256, smem>>>(x, out);
}